// round 10
// baseline (speedup 1.0000x reference)
#include <cuda_runtime.h>

#define Bb 2
#define Nn 8192
#define Ff 64
#define Oo 64
#define GRID 64
#define GPB  32          // blocks per batch (barrier group size)
#define TPB 512
#define NWARP 16
#define RPB 256          // rows per block
#define NGRP 32          // row groups (TPB/16)
#define ITERS 8          // RPB / NGRP

// Epoch-parity double-buffered accumulators: launch with epoch E uses slot E&1
// (zeroed by the previous launch / static init); lead block zeroes slot (E&1)^1
// at start for the NEXT launch.
__device__ __align__(16) float g_Sj[2][Bb];
__device__ __align__(16) float g_Pa[2][Bb * Oo];
__device__ __align__(16) float g_Qa[2][Bb * Oo];
__device__ unsigned long long g_ctr2[Bb];    // monotone per-batch barrier counters

__device__ __forceinline__ unsigned long long ctr_load_acq(const unsigned long long* p) {
    unsigned long long v;
    asm volatile("ld.acquire.gpu.global.u64 %0, [%1];" : "=l"(v) : "l"(p) : "memory");
    return v;
}
__device__ __forceinline__ unsigned long long ctr_load_cg(const unsigned long long* p) {
    unsigned long long v;
    asm volatile("ld.global.cg.u64 %0, [%1];" : "=l"(v) : "l"(p) : "memory");
    return v;
}
__device__ __forceinline__ float f_load_cg(const float* p) {
    float v;
    asm volatile("ld.global.cg.f32 %0, [%1];" : "=f"(v) : "l"(p) : "memory");
    return v;
}

__global__ void __launch_bounds__(TPB, 1) k_fused(
    const float* __restrict__ x, const float* __restrict__ adj_w,
    const float* __restrict__ adj_b, const float* __restrict__ weight,
    const float* __restrict__ bias, float* __restrict__ out)
{
    __shared__ float s_pu[NGRP * Ff];        // 8 KB
    __shared__ float s_pv[NGRP * Ff];        // 8 KB
    __shared__ float s_red[4][2 * Ff];       // quarter-sums
    __shared__ float s_uv[2 * Ff];           // u | v
    __shared__ float s_gp[4 * Oo];           // GEMM half partials
    __shared__ float sP[Oo], sQ[Oo], sB[Oo];
    __shared__ float s_W[Ff * Oo];           // 16 KB

    const int tid  = threadIdx.x;
    const int lane = tid & 15;               // feature quad
    const int grp  = tid >> 4;               // row group (0..31)
    const int bid  = blockIdx.x;
    const int bb   = bid >> 5;               // batch (32 blocks/batch)
    const int row0 = bid * RPB;

    // Epoch parity from the monotone counter (exact multiple of 2*GPB at entry;
    // floor-division is arrival-safe mid-launch too).
    const unsigned long long cv0 = ctr_load_cg(&g_ctr2[bb]);
    const int par = (int)((cv0 / (2ULL * GPB)) & 1ULL);

    // ---------------- x loads FIRST (critical DRAM path) ----------------------
    float4 xv[ITERS];
    #pragma unroll
    for (int it = 0; it < ITERS; ++it)
        xv[it] = reinterpret_cast<const float4*>(x)[(row0 + it * NGRP + grp) * 16 + lane];

    const float c = adj_b[0];
    const float4 wj = reinterpret_cast<const float4*>(adj_w)[lane];
    const float4 wi = reinterpret_cast<const float4*>(adj_w)[16 + lane];

    // Stage weight + bias (behind the x loads in issue order).
    #pragma unroll
    for (int k = 0; k < 2; ++k)
        reinterpret_cast<float4*>(s_W)[k * TPB + tid] =
            reinterpret_cast<const float4*>(weight)[k * TPB + tid];
    if (tid < Oo) sB[tid] = bias[tid];

    // Lead block per batch zeroes the NEXT launch's slots (off critical path).
    if ((bid & 31) == 0) {
        if (tid < Oo)            g_Pa[par ^ 1][bb * Oo + tid] = 0.0f;
        else if (tid < 2 * Oo)   g_Qa[par ^ 1][bb * Oo + tid - Oo] = 0.0f;
        else if (tid == 2 * Oo)  g_Sj[par ^ 1][bb] = 0.0f;
    }

    // ---------------- Phase 1a: warp Sj partial -> fire-and-forget RED --------
    float pjp[ITERS];
    float bl = 0.0f;
    #pragma unroll
    for (int it = 0; it < ITERS; ++it) {
        pjp[it] = xv[it].x * wj.x + xv[it].y * wj.y + xv[it].z * wj.z + xv[it].w * wj.w;
        bl += pjp[it];
    }
    #pragma unroll
    for (int off = 16; off; off >>= 1)
        bl += __shfl_xor_sync(0xffffffffu, bl, off);
    if ((tid & 31) == 0) atomicAdd(&g_Sj[par][bb], bl);   // no return, no release
    __syncthreads();

    // ---------------- Barrier 1 ARRIVE (block-level, single fence) ------------
    unsigned long long b1t = 0;
    if (tid == 0) {
        __threadfence();                       // publish this block's Sj REDs
        unsigned long long token = atomicAdd(&g_ctr2[bb], 1ULL);
        unsigned long long E = token / (2ULL * GPB);
        b1t = E * (2ULL * GPB) + 1ULL * GPB;
    }

    // ---------------- Phase 1b: per-row folds (hidden under barrier wait) -----
    float rsj[ITERS], rsi[ITERS];
    #pragma unroll
    for (int it = 0; it < ITERS; ++it) {
        float pj = pjp[it];
        #pragma unroll
        for (int off = 8; off; off >>= 1)
            pj += __shfl_xor_sync(0xffffffffu, pj, off, 16);
        rsj[it] = pj;
    }
    #pragma unroll
    for (int it = 0; it < ITERS; ++it) {
        float pi = xv[it].x * wi.x + xv[it].y * wi.y + xv[it].z * wi.z + xv[it].w * wi.w;
        #pragma unroll
        for (int off = 8; off; off >>= 1)
            pi += __shfl_xor_sync(0xffffffffu, pi, off, 16);
        rsi[it] = pi;
    }

    // ---------------- Barrier 1 WAIT ------------------------------------------
    if (tid == 0) {
        while (ctr_load_cg(&g_ctr2[bb]) < b1t) __nanosleep(20);
        (void)ctr_load_acq(&g_ctr2[bb]);
    }
    __syncthreads();

    const float Sj = f_load_cg(&g_Sj[par][bb]);

    // ---------------- Phase 2: u/v block partials ------------------------------
    float4 au = make_float4(0.f, 0.f, 0.f, 0.f);
    float4 av = make_float4(0.f, 0.f, 0.f, 0.f);
    float rd[ITERS], ra[ITERS];
    #pragma unroll
    for (int it = 0; it < ITERS; ++it) {
        float d  = rsqrtf(fmaxf((float)Nn * (rsi[it] + c) + Sj, 1.0f));
        rd[it] = d;
        ra[it] = rsi[it] + c;
        float sd = rsj[it] * d;
        au.x += d  * xv[it].x;  au.y += d  * xv[it].y;
        au.z += d  * xv[it].z;  au.w += d  * xv[it].w;
        av.x += sd * xv[it].x;  av.y += sd * xv[it].y;
        av.z += sd * xv[it].z;  av.w += sd * xv[it].w;
    }
    reinterpret_cast<float4*>(s_pu)[grp * 16 + lane] = au;
    reinterpret_cast<float4*>(s_pv)[grp * 16 + lane] = av;
    __syncthreads();

    // Reduce: all 512 threads, 8-deep quarters.
    {
        const int col = tid & 127;           // 0..63 -> u, 64..127 -> v
        const int h   = tid >> 7;            // quarter 0..3
        const float* src = (col < 64) ? (s_pu + col) : (s_pv + (col - 64));
        float a = 0.f;
        #pragma unroll
        for (int g = 0; g < 8; ++g) a += src[(h * 8 + g) * Ff];
        s_red[h][col] = a;
    }
    __syncthreads();
    if (tid < 128)
        s_uv[tid] = (s_red[0][tid] + s_red[1][tid]) + (s_red[2][tid] + s_red[3][tid]);
    __syncthreads();

    // Micro-GEMM halves: 256 threads x 32 FMA; P,Q linear in u,v -> RED partials.
    if (tid < 256) {
        const int o   = tid & 63;
        const int sel = tid >> 6;            // 0,1 -> P halves ; 2,3 -> Q halves
        const int uvo = (sel >> 1) * 64;
        const int f0  = (sel & 1) * 32;
        float acc = 0.f;
        #pragma unroll
        for (int f = 0; f < 32; ++f)
            acc = fmaf(s_uv[uvo + f0 + f], s_W[(f0 + f) * Oo + o], acc);
        s_gp[sel * Oo + o] = acc;
    }
    __syncthreads();
    if (tid < 64) {
        atomicAdd(&g_Pa[par][bb * Oo + tid], s_gp[tid] + s_gp[Oo + tid]);
    } else if (tid < 128) {
        const int o = tid - 64;
        atomicAdd(&g_Qa[par][bb * Oo + o], s_gp[2 * Oo + o] + s_gp[3 * Oo + o]);
    }
    __syncthreads();

    // ---------------- Barrier 2 (block-level, single fence) --------------------
    if (tid == 0) {
        __threadfence();
        unsigned long long token = atomicAdd(&g_ctr2[bb], 1ULL);
        unsigned long long E = token / (2ULL * GPB);
        unsigned long long t2 = E * (2ULL * GPB) + 2ULL * GPB;
        while (ctr_load_cg(&g_ctr2[bb]) < t2) __nanosleep(20);
        (void)ctr_load_acq(&g_ctr2[bb]);
    }
    __syncthreads();

    // ---------------- Phase 3: stage final P,Q ---------------------------------
    if (tid < 64)        sP[tid]      = f_load_cg(&g_Pa[par][bb * Oo + tid]);
    else if (tid < 128)  sQ[tid - 64] = f_load_cg(&g_Qa[par][bb * Oo + tid - 64]);
    __syncthreads();

    // ---------------- Phase 4: rank-1 epilogue ----------------------------------
    const int o4 = lane * 4;
    const float P0 = sP[o4 + 0], P1 = sP[o4 + 1], P2 = sP[o4 + 2], P3 = sP[o4 + 3];
    const float Q0 = sQ[o4 + 0], Q1 = sQ[o4 + 1], Q2 = sQ[o4 + 2], Q3 = sQ[o4 + 3];
    const float B0 = sB[o4 + 0], B1 = sB[o4 + 1], B2 = sB[o4 + 2], B3 = sB[o4 + 3];
    #pragma unroll
    for (int it = 0; it < ITERS; ++it) {
        const float d = rd[it];
        const float a = ra[it];
        float4 r;
        r.x = fmaxf(fmaf(d, fmaf(a, P0, Q0), B0), 0.0f);
        r.y = fmaxf(fmaf(d, fmaf(a, P1, Q1), B1), 0.0f);
        r.z = fmaxf(fmaf(d, fmaf(a, P2, Q2), B2), 0.0f);
        r.w = fmaxf(fmaf(d, fmaf(a, P3, Q3), B3), 0.0f);
        reinterpret_cast<float4*>(out)[(row0 + it * NGRP + grp) * 16 + lane] = r;
    }
}

extern "C" void kernel_launch(void* const* d_in, const int* in_sizes, int n_in,
                              void* d_out, int out_size) {
    const float* x      = (const float*)d_in[0];
    const float* adj_w  = (const float*)d_in[1];
    const float* adj_b  = (const float*)d_in[2];
    const float* weight = (const float*)d_in[3];
    const float* bias   = (const float*)d_in[4];
    float* out = (float*)d_out;

    k_fused<<<GRID, TPB>>>(x, adj_w, adj_b, weight, bias, out);
}

// round 11
// speedup vs baseline: 1.2149x; 1.2149x over previous
#include <cuda_runtime.h>

#define Bb 2
#define Nn 8192
#define Ff 64
#define Oo 64
#define GRID 64
#define GPB  32          // blocks per batch (barrier group size)
#define TPB 512
#define NWARP 16
#define RPB 256          // rows per block
#define NGRP 32          // row groups (TPB/16)
#define ITERS 8          // RPB / NGRP

// Epoch-parity double-buffered accumulators: launch with epoch E uses slot E&1
// (zeroed by the previous launch / static init); lead block zeroes slot (E&1)^1
// at start for the NEXT launch.
__device__ __align__(16) float g_Sj[2][Bb];
__device__ __align__(16) float g_Pa[2][Bb * Oo];
__device__ __align__(16) float g_Qa[2][Bb * Oo];
__device__ unsigned long long g_ctr2[Bb];    // monotone per-batch barrier counters

__device__ __forceinline__ unsigned long long ctr_load_acq(const unsigned long long* p) {
    unsigned long long v;
    asm volatile("ld.acquire.gpu.global.u64 %0, [%1];" : "=l"(v) : "l"(p) : "memory");
    return v;
}
__device__ __forceinline__ unsigned long long ctr_load_cg(const unsigned long long* p) {
    unsigned long long v;
    asm volatile("ld.global.cg.u64 %0, [%1];" : "=l"(v) : "l"(p) : "memory");
    return v;
}
__device__ __forceinline__ float f_load_cg(const float* p) {
    float v;
    asm volatile("ld.global.cg.f32 %0, [%1];" : "=f"(v) : "l"(p) : "memory");
    return v;
}

__global__ void __launch_bounds__(TPB, 1) k_fused(
    const float* __restrict__ x, const float* __restrict__ adj_w,
    const float* __restrict__ adj_b, const float* __restrict__ weight,
    const float* __restrict__ bias, float* __restrict__ out)
{
    __shared__ float s_pu[NGRP * Ff];        // 8 KB
    __shared__ float s_pv[NGRP * Ff];        // 8 KB
    __shared__ float s_u[Ff], s_v[Ff];
    __shared__ float sB[Oo];
    __shared__ float s_W[Ff * Oo];           // 16 KB
    __shared__ float s_wsum[NWARP];

    const int tid  = threadIdx.x;
    const int lane = tid & 15;               // feature quad
    const int grp  = tid >> 4;               // row group (0..31)
    const int wid  = tid >> 5;
    const int bid  = blockIdx.x;
    const int bb   = bid >> 5;               // batch (32 blocks/batch)
    const int row0 = bid * RPB;

    // Epoch parity from the monotone counter (exact multiple of 2*GPB at entry).
    const unsigned long long cv0 = ctr_load_cg(&g_ctr2[bb]);
    const int par = (int)((cv0 / (2ULL * GPB)) & 1ULL);

    const float c = adj_b[0];

    // Stage weight + bias (hidden under the phase-1 x load).
    #pragma unroll
    for (int k = 0; k < Ff * Oo / TPB; ++k)
        s_W[k * TPB + tid] = weight[k * TPB + tid];
    if (tid < Oo) sB[tid] = bias[tid];

    // Lead block per batch zeroes the NEXT launch's slots (off critical path).
    if ((bid & 31) == 0) {
        if (tid < Oo)            g_Pa[par ^ 1][bb * Oo + tid] = 0.0f;
        else if (tid < 2 * Oo)   g_Qa[par ^ 1][bb * Oo + tid - Oo] = 0.0f;
        else if (tid == 2 * Oo)  g_Sj[par ^ 1][bb] = 0.0f;
    }

    // ---------------- Phase 1a: lane-partial sj sums only --------------------
    float4 xv[ITERS];
    #pragma unroll
    for (int it = 0; it < ITERS; ++it)
        xv[it] = reinterpret_cast<const float4*>(x)[(row0 + it * NGRP + grp) * 16 + lane];

    const float4 wj = reinterpret_cast<const float4*>(adj_w)[lane];
    const float4 wi = reinterpret_cast<const float4*>(adj_w)[16 + lane];

    float pjp[ITERS];
    float bl = 0.0f;                         // per-lane partial of block Sj
    #pragma unroll
    for (int it = 0; it < ITERS; ++it) {
        pjp[it] = xv[it].x * wj.x + xv[it].y * wj.y + xv[it].z * wj.z + xv[it].w * wj.w;
        bl += pjp[it];
    }
    #pragma unroll
    for (int off = 16; off; off >>= 1)       // one warp fold, not per-row folds
        bl += __shfl_xor_sync(0xffffffffu, bl, off);
    if ((tid & 31) == 0) s_wsum[wid] = bl;
    __syncthreads();

    // ---------------- Barrier 1 ARRIVE (Sj RED folded into arrival) ----------
    unsigned long long b1t = 0;
    if (tid == 0) {
        float s = 0.f;
        #pragma unroll
        for (int w = 0; w < NWARP; ++w) s += s_wsum[w];
        atomicAdd(&g_Sj[par][bb], s);
        __threadfence();
        unsigned long long token = atomicAdd(&g_ctr2[bb], 1ULL);
        unsigned long long E = token / (2ULL * GPB);
        b1t = E * (2ULL * GPB) + 1ULL * GPB;
    }

    // ---------------- Phase 1b: per-row folds (hidden under barrier wait) ----
    float rsj[ITERS], rsi[ITERS];
    #pragma unroll
    for (int it = 0; it < ITERS; ++it) {
        float pj = pjp[it];
        #pragma unroll
        for (int off = 8; off; off >>= 1)
            pj += __shfl_xor_sync(0xffffffffu, pj, off, 16);
        rsj[it] = pj;
    }
    #pragma unroll
    for (int it = 0; it < ITERS; ++it) {
        float pi = xv[it].x * wi.x + xv[it].y * wi.y + xv[it].z * wi.z + xv[it].w * wi.w;
        #pragma unroll
        for (int off = 8; off; off >>= 1)
            pi += __shfl_xor_sync(0xffffffffu, pi, off, 16);
        rsi[it] = pi;
    }

    // ---------------- Barrier 1 WAIT (acquire poll, as in R7) ----------------
    if (tid == 0) {
        while (ctr_load_acq(&g_ctr2[bb]) < b1t) __nanosleep(20);
    }
    __syncthreads();

    const float Sj = f_load_cg(&g_Sj[par][bb]);   // single L2 load

    // ---------------- Phase 2: u/v block partials -----------------------------
    float4 au = make_float4(0.f, 0.f, 0.f, 0.f);
    float4 av = make_float4(0.f, 0.f, 0.f, 0.f);
    float rd[ITERS], ra[ITERS];
    #pragma unroll
    for (int it = 0; it < ITERS; ++it) {
        float d  = rsqrtf(fmaxf((float)Nn * (rsi[it] + c) + Sj, 1.0f));
        rd[it] = d;
        ra[it] = rsi[it] + c;
        float sd = rsj[it] * d;
        au.x += d  * xv[it].x;  au.y += d  * xv[it].y;
        au.z += d  * xv[it].z;  au.w += d  * xv[it].w;
        av.x += sd * xv[it].x;  av.y += sd * xv[it].y;
        av.z += sd * xv[it].z;  av.w += sd * xv[it].w;
    }
    reinterpret_cast<float4*>(s_pu)[grp * 16 + lane] = au;
    reinterpret_cast<float4*>(s_pv)[grp * 16 + lane] = av;
    __syncthreads();
    if (tid < 64) {
        float a = 0.f;
        #pragma unroll
        for (int g = 0; g < NGRP; ++g) a += s_pu[g * Ff + tid];
        s_u[tid] = a;
    } else if (tid < 128) {
        int f = tid - 64;
        float a = 0.f;
        #pragma unroll
        for (int g = 0; g < NGRP; ++g) a += s_pv[g * Ff + f];
        s_v[f] = a;
    }
    __syncthreads();

    // ---------------- Local micro-GEMM + RED of P,Q (P linear in u) ----------
    if (tid < 64) {
        float p0 = 0.f, p1 = 0.f;
        #pragma unroll
        for (int f = 0; f < 32; ++f) {
            p0 = fmaf(s_u[f],      s_W[f * Oo + tid],        p0);
            p1 = fmaf(s_u[f + 32], s_W[(f + 32) * Oo + tid], p1);
        }
        atomicAdd(&g_Pa[par][bb * Oo + tid], p0 + p1);
    } else if (tid < 128) {
        int o = tid - 64;
        float q0 = 0.f, q1 = 0.f;
        #pragma unroll
        for (int f = 0; f < 32; ++f) {
            q0 = fmaf(s_v[f],      s_W[f * Oo + o],        q0);
            q1 = fmaf(s_v[f + 32], s_W[(f + 32) * Oo + o], q1);
        }
        atomicAdd(&g_Qa[par][bb * Oo + o], q0 + q1);
    }
    __syncthreads();

    // ---------------- Barrier 2 (single release fence at arrival) -------------
    if (tid == 0) {
        __threadfence();                      // publish this block's P/Q REDs
        unsigned long long token = atomicAdd(&g_ctr2[bb], 1ULL);
        unsigned long long E = token / (2ULL * GPB);
        unsigned long long t2 = E * (2ULL * GPB) + 2ULL * GPB;
        while (ctr_load_acq(&g_ctr2[bb]) < t2) __nanosleep(20);
    }
    __syncthreads();

    // ---------------- Phase 4: rank-1 epilogue (direct P/Q loads) -------------
    const int o4 = lane * 4;
    const float4 Pv = __ldcg(reinterpret_cast<const float4*>(&g_Pa[par][bb * Oo + o4]));
    const float4 Qv = __ldcg(reinterpret_cast<const float4*>(&g_Qa[par][bb * Oo + o4]));
    const float B0 = sB[o4 + 0], B1 = sB[o4 + 1], B2 = sB[o4 + 2], B3 = sB[o4 + 3];
    #pragma unroll
    for (int it = 0; it < ITERS; ++it) {
        const float d = rd[it];
        const float a = ra[it];
        float4 r;
        r.x = fmaxf(fmaf(d, fmaf(a, Pv.x, Qv.x), B0), 0.0f);
        r.y = fmaxf(fmaf(d, fmaf(a, Pv.y, Qv.y), B1), 0.0f);
        r.z = fmaxf(fmaf(d, fmaf(a, Pv.z, Qv.z), B2), 0.0f);
        r.w = fmaxf(fmaf(d, fmaf(a, Pv.w, Qv.w), B3), 0.0f);
        reinterpret_cast<float4*>(out)[(row0 + it * NGRP + grp) * 16 + lane] = r;
    }
}

extern "C" void kernel_launch(void* const* d_in, const int* in_sizes, int n_in,
                              void* d_out, int out_size) {
    const float* x      = (const float*)d_in[0];
    const float* adj_w  = (const float*)d_in[1];
    const float* adj_b  = (const float*)d_in[2];
    const float* weight = (const float*)d_in[3];
    const float* bias   = (const float*)d_in[4];
    float* out = (float*)d_out;

    k_fused<<<GRID, TPB>>>(x, adj_w, adj_b, weight, bias, out);
}